// round 1
// baseline (speedup 1.0000x reference)
#include <cuda_runtime.h>
#include <cstdint>

// Problem constants
constexpr int M = 16384;   // batch
constexpr int N = 1024;    // out features
constexpr int K = 1024;    // in features
constexpr int NB = 128;    // n_blocks
// jac output: NB * 8 * 8 = 8192 floats appended after y

// Scratch for normalized weights (4 MB) — static device global (no allocs allowed)
__device__ float g_Wn[N * K];

// ---------------------------------------------------------------------------
// Kernel 1: weight normalization + jacobian-log output
//   Wm = exp(W)*diag_mask + W*tril_mask
//   norm_r = ||Wm[r,:]||_2
//   Wn = exp(ls_r) * Wm / norm_r
//   jac[blk, a, b] = log(Wn[blk*8+a, blk*8+b]) = W + ls - log(norm)
// One block (256 threads) per row.
// ---------------------------------------------------------------------------
__global__ void prep_kernel(const float* __restrict__ W,
                            const float* __restrict__ ls,
                            const int* __restrict__ dmask,
                            const int* __restrict__ tmask,
                            float* __restrict__ jac) {
    int r = blockIdx.x;
    int t = threadIdx.x;
    const int rowoff = r * K;

    float wm[4];
    float ss = 0.f;
#pragma unroll
    for (int i = 0; i < 4; i++) {
        int c = t + i * 256;
        float w = W[rowoff + c];
        float v = dmask[rowoff + c] ? expf(w) : (tmask[rowoff + c] ? w : 0.f);
        wm[i] = v;
        ss += v * v;
    }

    // block reduction of sum-of-squares
    __shared__ float warpsum[8];
    __shared__ float s_norm;
#pragma unroll
    for (int o = 16; o > 0; o >>= 1) ss += __shfl_xor_sync(0xffffffffu, ss, o);
    if ((t & 31) == 0) warpsum[t >> 5] = ss;
    __syncthreads();
    if (t == 0) {
        float s = 0.f;
#pragma unroll
        for (int i = 0; i < 8; i++) s += warpsum[i];
        s_norm = sqrtf(s);
    }
    __syncthreads();

    float norm  = s_norm;
    float lsr   = ls[r];
    float scale = expf(lsr) / norm;
    int blk = r >> 3;
    int c_lo = blk * 8, c_hi = c_lo + 8;

#pragma unroll
    for (int i = 0; i < 4; i++) {
        int c = t + i * 256;
        g_Wn[rowoff + c] = wm[i] * scale;
        if (c >= c_lo && c < c_hi) {
            // exact: log(exp(W)*exp(ls)/norm) = W + ls - log(norm)
            jac[blk * 64 + (r & 7) * 8 + (c - c_lo)] = W[rowoff + c] + lsr - logf(norm);
        }
    }
}

// ---------------------------------------------------------------------------
// Kernel 2: y = x @ Wn^T + bias  (fp32, tiled SGEMM)
//   A = x [M x K] row-major, B = g_Wn [N x K] row-major (both K-major, NT gemm)
//   Block-triangular sparsity: for output feature tile starting at n0,
//   Wn rows n0..n0+127 have nonzeros only in cols < n0+128 -> Kmax = n0+BN.
// 128x128 tile, BK=16, 8x8 per-thread microtile, 256 threads.
// ---------------------------------------------------------------------------
constexpr int BM = 128, BN = 128, BK = 16;

__global__ __launch_bounds__(256, 2)
void gemm_kernel(const float* __restrict__ A,
                 const float* __restrict__ bias,
                 float* __restrict__ C) {
    __shared__ float As[BK][BM];
    __shared__ float Bs[BK][BN];

    // reverse n-tile order so heaviest tiles (largest Kmax) schedule first
    int ntile = (int)gridDim.x - 1 - (int)blockIdx.x;
    int n0 = ntile * BN;
    int m0 = blockIdx.y * BM;
    int Kmax = n0 + BN;   // <= 1024, multiple of BK

    int tid = threadIdx.x;
    int tx = tid & 15;    // 0..15 -> output cols tx*8..+8
    int ty = tid >> 4;    // 0..15 -> output rows ty*8..+8

    const float* Aptr = A + (size_t)m0 * K;
    const float* Bptr = g_Wn + (size_t)n0 * K;

    float acc[8][8];
#pragma unroll
    for (int i = 0; i < 8; i++)
#pragma unroll
        for (int j = 0; j < 8; j++) acc[i][j] = 0.f;

    for (int k0 = 0; k0 < Kmax; k0 += BK) {
        // load A tile: 128 rows x 16 cols = 512 float4s, transposed into As[k][m]
#pragma unroll
        for (int v = tid; v < 512; v += 256) {
            int row = v >> 2, c4 = v & 3;
            float4 f = *(const float4*)(Aptr + (size_t)row * K + k0 + c4 * 4);
            As[c4 * 4 + 0][row] = f.x;
            As[c4 * 4 + 1][row] = f.y;
            As[c4 * 4 + 2][row] = f.z;
            As[c4 * 4 + 3][row] = f.w;
        }
        // load B tile (Wn rows n0..n0+127), transposed into Bs[k][n]
#pragma unroll
        for (int v = tid; v < 512; v += 256) {
            int row = v >> 2, c4 = v & 3;
            float4 f = *(const float4*)(Bptr + (size_t)row * K + k0 + c4 * 4);
            Bs[c4 * 4 + 0][row] = f.x;
            Bs[c4 * 4 + 1][row] = f.y;
            Bs[c4 * 4 + 2][row] = f.z;
            Bs[c4 * 4 + 3][row] = f.w;
        }
        __syncthreads();

#pragma unroll
        for (int k = 0; k < BK; k++) {
            float a[8], b[8];
            *(float4*)(a)     = *(const float4*)&As[k][ty * 8];
            *(float4*)(a + 4) = *(const float4*)&As[k][ty * 8 + 4];
            *(float4*)(b)     = *(const float4*)&Bs[k][tx * 8];
            *(float4*)(b + 4) = *(const float4*)&Bs[k][tx * 8 + 4];
#pragma unroll
            for (int i = 0; i < 8; i++)
#pragma unroll
                for (int j = 0; j < 8; j++)
                    acc[i][j] += a[i] * b[j];
        }
        __syncthreads();
    }

    // epilogue: add bias, store
#pragma unroll
    for (int i = 0; i < 8; i++) {
        int m = m0 + ty * 8 + i;
#pragma unroll
        for (int j = 0; j < 8; j += 4) {
            int n = n0 + tx * 8 + j;
            float4 o;
            o.x = acc[i][j + 0] + bias[n + 0];
            o.y = acc[i][j + 1] + bias[n + 1];
            o.z = acc[i][j + 2] + bias[n + 2];
            o.w = acc[i][j + 3] + bias[n + 3];
            *(float4*)(C + (size_t)m * N + n) = o;
        }
    }
}

// ---------------------------------------------------------------------------
// Launch: inputs in metadata order: x, W, bias, W_log_scale, b_diag_mask, b_tril_mask
// Output: y [16384*1024] floats, then jac [8192] floats
// ---------------------------------------------------------------------------
extern "C" void kernel_launch(void* const* d_in, const int* in_sizes, int n_in,
                              void* d_out, int out_size) {
    const float* x     = (const float*)d_in[0];
    const float* W     = (const float*)d_in[1];
    const float* bias  = (const float*)d_in[2];
    const float* ls    = (const float*)d_in[3];
    const int*   dmask = (const int*)d_in[4];
    const int*   tmask = (const int*)d_in[5];

    float* y   = (float*)d_out;
    float* jac = y + (size_t)M * N;

    prep_kernel<<<N, 256>>>(W, ls, dmask, tmask, jac);
    gemm_kernel<<<dim3(N / BN, M / BM), 256>>>(x, bias, y);
}

// round 5
// speedup vs baseline: 2.4820x; 2.4820x over previous
#include <cuda_runtime.h>
#include <cuda_bf16.h>
#include <cstdint>

// Problem constants
constexpr int M = 16384;   // batch
constexpr int N = 1024;    // out features
constexpr int K = 1024;    // in features

// GEMM tiling
constexpr int BM = 128, BN = 128, BK = 32;
constexpr int ROWB = 80;   // bytes per SMEM row (64B data + 16B pad: conflict-free ldmatrix)

// Scratch for normalized weights (4 MB)
__device__ float g_Wn[N * K];

// ---------------------------------------------------------------------------
// Kernel 1: weight normalization + jacobian-log output
// ---------------------------------------------------------------------------
__global__ void prep_kernel(const float* __restrict__ W,
                            const float* __restrict__ ls,
                            const int* __restrict__ dmask,
                            const int* __restrict__ tmask,
                            float* __restrict__ jac) {
    int r = blockIdx.x;
    int t = threadIdx.x;
    const int rowoff = r * K;

    float wm[4];
    float ss = 0.f;
#pragma unroll
    for (int i = 0; i < 4; i++) {
        int c = t + i * 256;
        float w = W[rowoff + c];
        float v = dmask[rowoff + c] ? expf(w) : (tmask[rowoff + c] ? w : 0.f);
        wm[i] = v;
        ss += v * v;
    }

    __shared__ float warpsum[8];
    __shared__ float s_norm;
#pragma unroll
    for (int o = 16; o > 0; o >>= 1) ss += __shfl_xor_sync(0xffffffffu, ss, o);
    if ((t & 31) == 0) warpsum[t >> 5] = ss;
    __syncthreads();
    if (t == 0) {
        float s = 0.f;
#pragma unroll
        for (int i = 0; i < 8; i++) s += warpsum[i];
        s_norm = sqrtf(s);
    }
    __syncthreads();

    float norm  = s_norm;
    float lsr   = ls[r];
    float scale = expf(lsr) / norm;
    int blk = r >> 3;
    int c_lo = blk * 8, c_hi = c_lo + 8;

#pragma unroll
    for (int i = 0; i < 4; i++) {
        int c = t + i * 256;
        g_Wn[rowoff + c] = wm[i] * scale;
        if (c >= c_lo && c < c_hi) {
            jac[blk * 64 + (r & 7) * 8 + (c - c_lo)] = W[rowoff + c] + lsr - logf(norm);
        }
    }
}

// ---------------------------------------------------------------------------
// mma.sync / ldmatrix helpers (sm_80+ features, legal on plain sm_103)
// ---------------------------------------------------------------------------
__device__ __forceinline__ uint32_t smem_u32(const void* p) {
    uint32_t a;
    asm("{ .reg .u64 t; cvta.to.shared.u64 t, %1; cvt.u32.u64 %0, t; }" : "=r"(a) : "l"(p));
    return a;
}

__device__ __forceinline__ void ldsm_x4(uint32_t& r0, uint32_t& r1, uint32_t& r2, uint32_t& r3,
                                        uint32_t addr) {
    asm volatile("ldmatrix.sync.aligned.m8n8.x4.shared.b16 {%0,%1,%2,%3}, [%4];"
                 : "=r"(r0), "=r"(r1), "=r"(r2), "=r"(r3) : "r"(addr));
}

__device__ __forceinline__ void mma_16816(float* d, const uint32_t* a, const uint32_t* b) {
    asm volatile(
        "mma.sync.aligned.m16n8k16.row.col.f32.bf16.bf16.f32 "
        "{%0,%1,%2,%3}, {%4,%5,%6,%7}, {%8,%9}, {%0,%1,%2,%3};"
        : "+f"(d[0]), "+f"(d[1]), "+f"(d[2]), "+f"(d[3])
        : "r"(a[0]), "r"(a[1]), "r"(a[2]), "r"(a[3]), "r"(b[0]), "r"(b[1]));
}

// ---------------------------------------------------------------------------
// Kernel 2: split-bf16 HMMA GEMM  y = x @ Wn^T + bias
// CTA: 128x128 tile, BK=32. 8 warps as 2(M)x4(N) -> warp tile 64x32.
// Per k16-step: 3 mma products (AhBh + AhBl + AlBh) into fp32 acc.
// Block-triangular: Kmax = n0 + 128.
// ---------------------------------------------------------------------------
__global__ __launch_bounds__(256, 2)
void gemm_mma(const float* __restrict__ A,
              const float* __restrict__ bias,
              float* __restrict__ C) {
    __shared__ __align__(16) char sm_ah[BM * ROWB];
    __shared__ __align__(16) char sm_al[BM * ROWB];
    __shared__ __align__(16) char sm_bh[BN * ROWB];
    __shared__ __align__(16) char sm_bl[BN * ROWB];

    const int tid  = threadIdx.x;
    const int wid  = tid >> 5;
    const int lane = tid & 31;

    // heavy n-tiles first
    const int ntile = 7 - (int)blockIdx.x;
    const int n0 = ntile * BN;
    const int m0 = (int)blockIdx.y * BM;
    const int Kmax = n0 + BN;          // multiple of BK

    const int wm = wid & 1;            // 0..1  (M)
    const int wn = wid >> 1;           // 0..3  (N)

    const uint32_t ah_b = smem_u32(sm_ah);
    const uint32_t al_b = smem_u32(sm_al);
    const uint32_t bh_b = smem_u32(sm_bh);
    const uint32_t bl_b = smem_u32(sm_bl);

    const float* Abase = A    + (size_t)m0 * K;
    const float* Bbase = g_Wn + (size_t)n0 * K;

    float acc[4][4][4];
#pragma unroll
    for (int i = 0; i < 4; i++)
#pragma unroll
        for (int j = 0; j < 4; j++)
#pragma unroll
            for (int r = 0; r < 4; r++) acc[i][j][r] = 0.f;

    for (int k0 = 0; k0 < Kmax; k0 += BK) {
        // ---- fill SMEM: fp32 -> bf16 hi/lo, rows padded to 80B ----
#pragma unroll
        for (int i = 0; i < 4; i++) {
            int v   = tid + i * 256;           // 0..1023
            int row = v >> 3;                  // 0..127
            int c4  = v & 7;                   // float4 column
            uint32_t soff = (uint32_t)(row * ROWB + c4 * 8);

            float4 fa = *(const float4*)(Abase + (size_t)row * K + k0 + c4 * 4);
            __nv_bfloat162 h0 = __float22bfloat162_rn(make_float2(fa.x, fa.y));
            __nv_bfloat162 h1 = __float22bfloat162_rn(make_float2(fa.z, fa.w));
            __nv_bfloat162 l0 = __float22bfloat162_rn(make_float2(
                fa.x - __bfloat162float(h0.x), fa.y - __bfloat162float(h0.y)));
            __nv_bfloat162 l1 = __float22bfloat162_rn(make_float2(
                fa.z - __bfloat162float(h1.x), fa.w - __bfloat162float(h1.y)));
            asm volatile("st.shared.v2.b32 [%0], {%1, %2};"
                         :: "r"(ah_b + soff), "r"(*(uint32_t*)&h0), "r"(*(uint32_t*)&h1) : "memory");
            asm volatile("st.shared.v2.b32 [%0], {%1, %2};"
                         :: "r"(al_b + soff), "r"(*(uint32_t*)&l0), "r"(*(uint32_t*)&l1) : "memory");

            float4 fb = *(const float4*)(Bbase + (size_t)row * K + k0 + c4 * 4);
            __nv_bfloat162 g0 = __float22bfloat162_rn(make_float2(fb.x, fb.y));
            __nv_bfloat162 g1 = __float22bfloat162_rn(make_float2(fb.z, fb.w));
            __nv_bfloat162 m0v = __float22bfloat162_rn(make_float2(
                fb.x - __bfloat162float(g0.x), fb.y - __bfloat162float(g0.y)));
            __nv_bfloat162 m1v = __float22bfloat162_rn(make_float2(
                fb.z - __bfloat162float(g1.x), fb.w - __bfloat162float(g1.y)));
            asm volatile("st.shared.v2.b32 [%0], {%1, %2};"
                         :: "r"(bh_b + soff), "r"(*(uint32_t*)&g0), "r"(*(uint32_t*)&g1) : "memory");
            asm volatile("st.shared.v2.b32 [%0], {%1, %2};"
                         :: "r"(bl_b + soff), "r"(*(uint32_t*)&m0v), "r"(*(uint32_t*)&m1v) : "memory");
        }
        __syncthreads();

        // ---- MMA over two k16 steps ----
#pragma unroll
        for (int ks = 0; ks < 2; ks++) {
            const uint32_t kbyte = ks * 32;    // within-chunk k byte offset

            // B fragments: 2 ldmatrix.x4 per split cover the 4 n8 tiles
            uint32_t bh[4][2], bl[4][2];
            {
                int nrow = (lane & 7) + ((lane & 16) ? 8 : 0);
                uint32_t kseg = ((lane >> 3) & 1) * 16;
#pragma unroll
                for (int half = 0; half < 2; half++) {
                    uint32_t addr_off = (uint32_t)((wn * 32 + half * 16 + nrow) * ROWB) + kbyte + kseg;
                    ldsm_x4(bh[half*2][0], bh[half*2][1], bh[half*2+1][0], bh[half*2+1][1],
                            bh_b + addr_off);
                    ldsm_x4(bl[half*2][0], bl[half*2][1], bl[half*2+1][0], bl[half*2+1][1],
                            bl_b + addr_off);
                }
            }

            // A fragments per m16 tile, then 3 products
            int mrow = lane & 15;
            uint32_t akseg = (uint32_t)(lane >> 4) * 16;
#pragma unroll
            for (int mi = 0; mi < 4; mi++) {
                uint32_t aoff = (uint32_t)((wm * 64 + mi * 16 + mrow) * ROWB) + kbyte + akseg;
                uint32_t ah[4], al[4];
                ldsm_x4(ah[0], ah[1], ah[2], ah[3], ah_b + aoff);
                ldsm_x4(al[0], al[1], al[2], al[3], al_b + aoff);
#pragma unroll
                for (int nj = 0; nj < 4; nj++) {
                    mma_16816(acc[mi][nj], ah, bh[nj]);
                    mma_16816(acc[mi][nj], ah, bl[nj]);
                    mma_16816(acc[mi][nj], al, bh[nj]);
                }
            }
        }
        __syncthreads();
    }

    // ---- epilogue: add bias, store ----
    const int crow = lane >> 2;          // 0..7
    const int ccol = (lane & 3) * 2;     // 0,2,4,6
#pragma unroll
    for (int nj = 0; nj < 4; nj++) {
        int col = n0 + wn * 32 + nj * 8 + ccol;
        float2 bv = *(const float2*)(bias + col);
#pragma unroll
        for (int mi = 0; mi < 4; mi++) {
            int row = m0 + wm * 64 + mi * 16 + crow;
            float2 o0, o1;
            o0.x = acc[mi][nj][0] + bv.x;
            o0.y = acc[mi][nj][1] + bv.y;
            o1.x = acc[mi][nj][2] + bv.x;
            o1.y = acc[mi][nj][3] + bv.y;
            *(float2*)(C + (size_t)row * N + col)       = o0;
            *(float2*)(C + (size_t)(row + 8) * N + col) = o1;
        }
    }
}

// ---------------------------------------------------------------------------
// Launch
// ---------------------------------------------------------------------------
extern "C" void kernel_launch(void* const* d_in, const int* in_sizes, int n_in,
                              void* d_out, int out_size) {
    const float* x     = (const float*)d_in[0];
    const float* W     = (const float*)d_in[1];
    const float* bias  = (const float*)d_in[2];
    const float* ls    = (const float*)d_in[3];
    const int*   dmask = (const int*)d_in[4];
    const int*   tmask = (const int*)d_in[5];

    float* y   = (float*)d_out;
    float* jac = y + (size_t)M * N;

    prep_kernel<<<N, 256>>>(W, ls, dmask, tmask, jac);
    gemm_mma<<<dim3(N / BN, M / BM), 256>>>(x, bias, y);
}

// round 6
// speedup vs baseline: 2.9021x; 1.1692x over previous
#include <cuda_runtime.h>
#include <cuda_bf16.h>
#include <cstdint>

// Problem constants
constexpr int M = 16384;   // batch
constexpr int N = 1024;    // out features
constexpr int K = 1024;    // in features

// GEMM tiling
constexpr int BM = 128, BN = 128, BK = 32;
constexpr int ROWB = 80;     // bytes per SMEM row (64B data + 16B pad: conflict-free ldmatrix)

// SMEM stage layout (double buffered)
constexpr int T_AH = 0;
constexpr int T_AL = BM * ROWB;          // 10240
constexpr int T_BH = 2 * BM * ROWB;      // 20480
constexpr int T_BL = 3 * BM * ROWB;      // 30720
constexpr int STG  = 4 * BM * ROWB;      // 40960 per stage
constexpr int SMEM_TOTAL = 2 * STG;      // 81920

// Precomputed normalized-weight bf16 splits (4 MB total)
__device__ __nv_bfloat16 g_Bh[N * K];
__device__ __nv_bfloat16 g_Bl[N * K];

// ---------------------------------------------------------------------------
// Kernel 1: weight normalization -> bf16 hi/lo splits + jacobian-log output
// ---------------------------------------------------------------------------
__global__ void prep_kernel(const float* __restrict__ W,
                            const float* __restrict__ ls,
                            const int* __restrict__ dmask,
                            const int* __restrict__ tmask,
                            float* __restrict__ jac) {
    int r = blockIdx.x;
    int t = threadIdx.x;
    const int rowoff = r * K;

    float wm[4];
    float ss = 0.f;
#pragma unroll
    for (int i = 0; i < 4; i++) {
        int c = t + i * 256;
        float w = W[rowoff + c];
        float v = dmask[rowoff + c] ? expf(w) : (tmask[rowoff + c] ? w : 0.f);
        wm[i] = v;
        ss += v * v;
    }

    __shared__ float warpsum[8];
    __shared__ float s_norm;
#pragma unroll
    for (int o = 16; o > 0; o >>= 1) ss += __shfl_xor_sync(0xffffffffu, ss, o);
    if ((t & 31) == 0) warpsum[t >> 5] = ss;
    __syncthreads();
    if (t == 0) {
        float s = 0.f;
#pragma unroll
        for (int i = 0; i < 8; i++) s += warpsum[i];
        s_norm = sqrtf(s);
    }
    __syncthreads();

    float norm  = s_norm;
    float lsr   = ls[r];
    float scale = expf(lsr) / norm;
    int blk = r >> 3;
    int c_lo = blk * 8, c_hi = c_lo + 8;

#pragma unroll
    for (int i = 0; i < 4; i++) {
        int c = t + i * 256;
        float v = wm[i] * scale;
        __nv_bfloat16 hi = __float2bfloat16_rn(v);
        __nv_bfloat16 lo = __float2bfloat16_rn(v - __bfloat162float(hi));
        g_Bh[rowoff + c] = hi;
        g_Bl[rowoff + c] = lo;
        if (c >= c_lo && c < c_hi) {
            jac[blk * 64 + (r & 7) * 8 + (c - c_lo)] = W[rowoff + c] + lsr - logf(norm);
        }
    }
}

// ---------------------------------------------------------------------------
// PTX helpers
// ---------------------------------------------------------------------------
__device__ __forceinline__ uint32_t smem_u32(const void* p) {
    uint32_t a;
    asm("{ .reg .u64 t; cvta.to.shared.u64 t, %1; cvt.u32.u64 %0, t; }" : "=r"(a) : "l"(p));
    return a;
}

__device__ __forceinline__ void cp16(uint32_t dst, const void* src) {
    asm volatile("cp.async.cg.shared.global [%0], [%1], 16;" :: "r"(dst), "l"(src) : "memory");
}

__device__ __forceinline__ void ldsm_x4(uint32_t& r0, uint32_t& r1, uint32_t& r2, uint32_t& r3,
                                        uint32_t addr) {
    asm volatile("ldmatrix.sync.aligned.m8n8.x4.shared.b16 {%0,%1,%2,%3}, [%4];"
                 : "=r"(r0), "=r"(r1), "=r"(r2), "=r"(r3) : "r"(addr));
}

__device__ __forceinline__ void mma_16816(float* d, const uint32_t* a, const uint32_t* b) {
    asm volatile(
        "mma.sync.aligned.m16n8k16.row.col.f32.bf16.bf16.f32 "
        "{%0,%1,%2,%3}, {%4,%5,%6,%7}, {%8,%9}, {%0,%1,%2,%3};"
        : "+f"(d[0]), "+f"(d[1]), "+f"(d[2]), "+f"(d[3])
        : "r"(a[0]), "r"(a[1]), "r"(a[2]), "r"(a[3]), "r"(b[0]), "r"(b[1]));
}

// ---------------------------------------------------------------------------
// Kernel 2: software-pipelined split-bf16 HMMA GEMM  y = x @ Wn^T + bias
// CTA 128x128, BK=32, double-buffered SMEM; B via cp.async from precomputed
// bf16 splits; A LDG->reg prefetch + convert under MMA.
// ---------------------------------------------------------------------------
__global__ __launch_bounds__(256, 2)
void gemm_mma(const float* __restrict__ A,
              const float* __restrict__ bias,
              float* __restrict__ C) {
    extern __shared__ __align__(16) char smem[];
    const uint32_t sb = smem_u32(smem);

    const int tid  = threadIdx.x;
    const int wid  = tid >> 5;
    const int lane = tid & 31;

    // heavy n-tiles first
    const int ntile = 7 - (int)blockIdx.x;
    const int n0 = ntile * BN;
    const int m0 = (int)blockIdx.y * BM;
    const int Kmax = n0 + BN;
    const int nch  = Kmax / BK;

    const int wm = wid & 1;            // 0..1  (M)
    const int wn = wid >> 1;           // 0..3  (N)

    const float* Abase = A + (size_t)m0 * K;

    float acc[4][4][4];
#pragma unroll
    for (int i = 0; i < 4; i++)
#pragma unroll
        for (int j = 0; j < 4; j++)
#pragma unroll
            for (int r = 0; r < 4; r++) acc[i][j][r] = 0.f;

    // per-thread fixed fill coordinates
    const int a_c4  = tid & 7;         // float4 column in A tile
    const int a_r0  = tid >> 3;        // base row (stride 32)
    const int b_seg = tid & 3;         // 16B segment in B row
    const int b_r0  = tid >> 2;        // base row (stride 64)

    // ---- pipeline helpers --------------------------------------------------
    auto issueB = [&](int c, int st) {
        int k0 = c * BK;
#pragma unroll
        for (int i = 0; i < 2; i++) {
            int row = b_r0 + i * 64;
            uint32_t d = sb + st * STG + (uint32_t)(row * ROWB + b_seg * 16);
            size_t goff = (size_t)(n0 + row) * K + k0 + b_seg * 8;
            cp16(d + T_BH, g_Bh + goff);
            cp16(d + T_BL, g_Bl + goff);
        }
        asm volatile("cp.async.commit_group;" ::: "memory");
    };

    auto ldgA = [&](int c, float4* fa) {
        int k0 = c * BK;
#pragma unroll
        for (int i = 0; i < 4; i++) {
            int row = a_r0 + i * 32;
            fa[i] = *(const float4*)(Abase + (size_t)row * K + k0 + a_c4 * 4);
        }
    };

    auto storeA = [&](int st, const float4* fa) {
#pragma unroll
        for (int i = 0; i < 4; i++) {
            int row = a_r0 + i * 32;
            uint32_t soff = sb + st * STG + (uint32_t)(row * ROWB + a_c4 * 8);
            float4 f = fa[i];
            __nv_bfloat162 h0 = __float22bfloat162_rn(make_float2(f.x, f.y));
            __nv_bfloat162 h1 = __float22bfloat162_rn(make_float2(f.z, f.w));
            __nv_bfloat162 l0 = __float22bfloat162_rn(make_float2(
                f.x - __bfloat162float(h0.x), f.y - __bfloat162float(h0.y)));
            __nv_bfloat162 l1 = __float22bfloat162_rn(make_float2(
                f.z - __bfloat162float(h1.x), f.w - __bfloat162float(h1.y)));
            asm volatile("st.shared.v2.b32 [%0], {%1, %2};"
                         :: "r"(soff + T_AH), "r"(*(uint32_t*)&h0), "r"(*(uint32_t*)&h1) : "memory");
            asm volatile("st.shared.v2.b32 [%0], {%1, %2};"
                         :: "r"(soff + T_AL), "r"(*(uint32_t*)&l0), "r"(*(uint32_t*)&l1) : "memory");
        }
    };

    auto mmaStage = [&](int st) {
        const uint32_t ah_b = sb + st * STG + T_AH;
        const uint32_t al_b = sb + st * STG + T_AL;
        const uint32_t bh_b = sb + st * STG + T_BH;
        const uint32_t bl_b = sb + st * STG + T_BL;
#pragma unroll
        for (int ks = 0; ks < 2; ks++) {
            const uint32_t kbyte = ks * 32;

            uint32_t bh[4][2], bl[4][2];
            {
                int nrow = (lane & 7) + ((lane & 16) ? 8 : 0);
                uint32_t kseg = ((lane >> 3) & 1) * 16;
#pragma unroll
                for (int half = 0; half < 2; half++) {
                    uint32_t addr_off = (uint32_t)((wn * 32 + half * 16 + nrow) * ROWB) + kbyte + kseg;
                    ldsm_x4(bh[half*2][0], bh[half*2][1], bh[half*2+1][0], bh[half*2+1][1],
                            bh_b + addr_off);
                    ldsm_x4(bl[half*2][0], bl[half*2][1], bl[half*2+1][0], bl[half*2+1][1],
                            bl_b + addr_off);
                }
            }

            int mrow = lane & 15;
            uint32_t akseg = (uint32_t)(lane >> 4) * 16;
#pragma unroll
            for (int mi = 0; mi < 4; mi++) {
                uint32_t aoff = (uint32_t)((wm * 64 + mi * 16 + mrow) * ROWB) + kbyte + akseg;
                uint32_t ah[4], al[4];
                ldsm_x4(ah[0], ah[1], ah[2], ah[3], ah_b + aoff);
                ldsm_x4(al[0], al[1], al[2], al[3], al_b + aoff);
                // 3 independent nj sweeps -> spaced RAW chains on acc
#pragma unroll
                for (int nj = 0; nj < 4; nj++) mma_16816(acc[mi][nj], ah, bh[nj]);
#pragma unroll
                for (int nj = 0; nj < 4; nj++) mma_16816(acc[mi][nj], ah, bl[nj]);
#pragma unroll
                for (int nj = 0; nj < 4; nj++) mma_16816(acc[mi][nj], al, bh[nj]);
            }
        }
    };
    // ------------------------------------------------------------------------

    float4 fa[4];

    // prologue: fill stage 0
    issueB(0, 0);
    ldgA(0, fa);
    storeA(0, fa);
    asm volatile("cp.async.wait_group 0;" ::: "memory");
    __syncthreads();

    for (int c = 0; c < nch; ++c) {
        int s = c & 1;
        bool more = (c + 1 < nch);
        if (more) {
            issueB(c + 1, s ^ 1);
            ldgA(c + 1, fa);
        }
        mmaStage(s);
        if (more) {
            storeA(s ^ 1, fa);
            asm volatile("cp.async.wait_group 0;" ::: "memory");
        }
        __syncthreads();
    }

    // ---- epilogue: add bias, store ----
    const int crow = lane >> 2;
    const int ccol = (lane & 3) * 2;
#pragma unroll
    for (int nj = 0; nj < 4; nj++) {
        int col = n0 + wn * 32 + nj * 8 + ccol;
        float2 bv = *(const float2*)(bias + col);
#pragma unroll
        for (int mi = 0; mi < 4; mi++) {
            int row = m0 + wm * 64 + mi * 16 + crow;
            float2 o0, o1;
            o0.x = acc[mi][nj][0] + bv.x;
            o0.y = acc[mi][nj][1] + bv.y;
            o1.x = acc[mi][nj][2] + bv.x;
            o1.y = acc[mi][nj][3] + bv.y;
            *(float2*)(C + (size_t)row * N + col)       = o0;
            *(float2*)(C + (size_t)(row + 8) * N + col) = o1;
        }
    }
}

// ---------------------------------------------------------------------------
// Launch
// ---------------------------------------------------------------------------
extern "C" void kernel_launch(void* const* d_in, const int* in_sizes, int n_in,
                              void* d_out, int out_size) {
    const float* x     = (const float*)d_in[0];
    const float* W     = (const float*)d_in[1];
    const float* bias  = (const float*)d_in[2];
    const float* ls    = (const float*)d_in[3];
    const int*   dmask = (const int*)d_in[4];
    const int*   tmask = (const int*)d_in[5];

    float* y   = (float*)d_out;
    float* jac = y + (size_t)M * N;

    cudaFuncSetAttribute(gemm_mma, cudaFuncAttributeMaxDynamicSharedMemorySize, SMEM_TOTAL);

    prep_kernel<<<N, 256>>>(W, ls, dmask, tmask, jac);
    gemm_mma<<<dim3(N / BN, M / BM), 256, SMEM_TOTAL>>>(x, bias, y);
}